// round 13
// baseline (speedup 1.0000x reference)
#include <cuda_runtime.h>
#include <cuda_bf16.h>
#include <cstdint>

#define BATCH 64
#define CIN   512
#define PCH   256
#define COUT  1024
#define HW1   784
#define HW2   196
#define N1    (BATCH * HW1)   // 50176
#define N2    (BATCH * HW2)   // 12544
#define K2    (PCH * 9)       // 2304

// ---------------- scratch: ALL activations [K][N] row-major ------------------
__device__ __nv_bfloat16 g_xq [(size_t)CIN * N1];   // [c][n1]
__device__ __nv_bfloat16 g_xs [(size_t)CIN * N2];   // [c][n2]
__device__ __nv_bfloat16 g_y1 [(size_t)PCH * N1];   // [m][n1]
__device__ __nv_bfloat16 g_im2[(size_t)K2  * N2];   // [k][n2]
__device__ __nv_bfloat16 g_y2 [(size_t)PCH * N2];   // [m][n2]
__device__ __nv_bfloat16 g_w1q[PCH  * CIN];
__device__ __nv_bfloat16 g_w2q[PCH  * K2];
__device__ __nv_bfloat16 g_w3q[COUT * PCH];
__device__ __nv_bfloat16 g_wsq[COUT * CIN];
__device__ unsigned g_maxbits[4];

// ---------------- helpers -----------------------------------------------------
__device__ __forceinline__ uint32_t smem_u32(const void* p) {
    uint32_t a;
    asm("{ .reg .u64 t; cvta.to.shared.u64 t, %1; cvt.u32.u64 %0, t; }" : "=r"(a) : "l"(p));
    return a;
}
__device__ __forceinline__ void cp16s(uint32_t s, const void* g) {
    asm volatile("cp.async.cg.shared.global [%0],[%1],16;\n" :: "r"(s), "l"(g));
}
#define CP_COMMIT asm volatile("cp.async.commit_group;\n" ::: "memory")
#define CP_WAIT1  asm volatile("cp.async.wait_group 1;\n" ::: "memory")

__device__ __forceinline__ void ldsm_x4(uint32_t (&r)[4], uint32_t addr) {
    asm volatile("ldmatrix.sync.aligned.m8n8.x4.shared.b16 {%0,%1,%2,%3},[%4];\n"
                 : "=r"(r[0]), "=r"(r[1]), "=r"(r[2]), "=r"(r[3]) : "r"(addr));
}
__device__ __forceinline__ void ldsm_x4t(uint32_t (&r)[4], uint32_t addr) {
    asm volatile("ldmatrix.sync.aligned.m8n8.x4.trans.shared.b16 {%0,%1,%2,%3},[%4];\n"
                 : "=r"(r[0]), "=r"(r[1]), "=r"(r[2]), "=r"(r[3]) : "r"(addr));
}
__device__ __forceinline__ void hmma(float (&c)[4], const uint32_t (&a)[4],
                                     uint32_t b0, uint32_t b1) {
    asm volatile("mma.sync.aligned.m16n8k16.row.col.f32.bf16.bf16.f32 "
                 "{%0,%1,%2,%3},{%4,%5,%6,%7},{%8,%9},{%0,%1,%2,%3};\n"
                 : "+f"(c[0]), "+f"(c[1]), "+f"(c[2]), "+f"(c[3])
                 : "r"(a[0]), "r"(a[1]), "r"(a[2]), "r"(a[3]), "r"(b0), "r"(b1));
}

// ---------------- setup kernels ----------------------------------------------
__global__ void reset_kernel() {
    if (threadIdx.x < 4) g_maxbits[threadIdx.x] = 0u;
}

__global__ void maxabs_all(const float* __restrict__ w1, const float* __restrict__ w2,
                           const float* __restrict__ w3, const float* __restrict__ ws) {
    int slot = blockIdx.y;
    const float* src = slot == 0 ? w1 : slot == 1 ? w2 : slot == 2 ? w3 : ws;
    int n4 = (slot == 0 ? PCH * CIN : slot == 1 ? PCH * K2 : slot == 2 ? COUT * PCH : COUT * CIN) / 4;
    float m = 0.f;
    for (int i = blockIdx.x * blockDim.x + threadIdx.x; i < n4; i += gridDim.x * blockDim.x) {
        float4 v = reinterpret_cast<const float4*>(src)[i];
        m = fmaxf(m, fmaxf(fmaxf(fabsf(v.x), fabsf(v.y)), fmaxf(fabsf(v.z), fabsf(v.w))));
    }
    #pragma unroll
    for (int o = 16; o; o >>= 1) m = fmaxf(m, __shfl_xor_sync(0xffffffffu, m, o));
    __shared__ float sm[8];
    if ((threadIdx.x & 31) == 0) sm[threadIdx.x >> 5] = m;
    __syncthreads();
    if (threadIdx.x < 8) {
        m = sm[threadIdx.x];
        #pragma unroll
        for (int o = 4; o; o >>= 1) m = fmaxf(m, __shfl_xor_sync(0xffu, m, o));
        if (threadIdx.x == 0) atomicMax(&g_maxbits[slot], __float_as_uint(m));
    }
}

__global__ void quantw_all(const float* __restrict__ w1, const float* __restrict__ w2,
                           const float* __restrict__ w3, const float* __restrict__ ws) {
    int slot = blockIdx.y;
    const float* src = slot == 0 ? w1 : slot == 1 ? w2 : slot == 2 ? w3 : ws;
    __nv_bfloat16* dst = slot == 0 ? g_w1q : slot == 1 ? g_w2q : slot == 2 ? g_w3q : g_wsq;
    int n4 = (slot == 0 ? PCH * CIN : slot == 1 ? PCH * K2 : slot == 2 ? COUT * PCH : COUT * CIN) / 4;
    const float inv = 1.f / __uint_as_float(g_maxbits[slot]);
    for (int i = blockIdx.x * blockDim.x + threadIdx.x; i < n4; i += gridDim.x * blockDim.x) {
        float4 v = reinterpret_cast<const float4*>(src)[i];
        __nv_bfloat16 q[4];
        q[0] = __float2bfloat16(rintf(fminf(fmaxf(v.x * inv, -1.f), 1.f) * 127.f));
        q[1] = __float2bfloat16(rintf(fminf(fmaxf(v.y * inv, -1.f), 1.f) * 127.f));
        q[2] = __float2bfloat16(rintf(fminf(fmaxf(v.z * inv, -1.f), 1.f) * 127.f));
        q[3] = __float2bfloat16(rintf(fminf(fmaxf(v.w * inv, -1.f), 1.f) * 127.f));
        *reinterpret_cast<uint2*>(dst + (size_t)i * 4) = *reinterpret_cast<uint2*>(q);
    }
}

// streaming quantize: x[img][c][pix] -> g_xq[c][img*784+pix]; downsample -> g_xs
__global__ __launch_bounds__(256) void quantx(const float* __restrict__ x) {
    int idx = blockIdx.x * blockDim.x + threadIdx.x;   // (img, c, j) j = 4-pix chunk
    if (idx >= BATCH * CIN * 196) return;
    int j   = idx % 196;
    int c   = (idx / 196) % CIN;
    int img = idx / (196 * CIN);
    float4 v = *reinterpret_cast<const float4*>(x + ((size_t)img * CIN + c) * HW1 + j * 4);
    __nv_bfloat16 q[4];
    q[0] = __float2bfloat16(rintf(fminf(fmaxf(v.x * 2.f, -1.f), 1.f) * 127.f));
    q[1] = __float2bfloat16(rintf(fminf(fmaxf(v.y * 2.f, -1.f), 1.f) * 127.f));
    q[2] = __float2bfloat16(rintf(fminf(fmaxf(v.z * 2.f, -1.f), 1.f) * 127.f));
    q[3] = __float2bfloat16(rintf(fminf(fmaxf(v.w * 2.f, -1.f), 1.f) * 127.f));
    *reinterpret_cast<uint2*>(g_xq + (size_t)c * N1 + img * HW1 + j * 4) =
        *reinterpret_cast<uint2*>(q);
    int h = j / 7, w0 = (j % 7) * 4;     // 28 = 7 chunks * 4
    if (!(h & 1)) {
        __nv_bfloat16 d[2] = {q[0], q[2]};
        *reinterpret_cast<unsigned*>(g_xs + (size_t)c * N2 + img * HW2 +
                                     (h >> 1) * 14 + (w0 >> 1)) = *reinterpret_cast<unsigned*>(d);
    }
}

// smem-staged im2col: g_y1[c][n1] -> g_im2[c*9+rs][n2]
__global__ __launch_bounds__(256) void im2col_s() {
    __shared__ __nv_bfloat16 sm[16 * 784 + 8];
    int c0 = blockIdx.x * 16, img = blockIdx.y;
    int t = threadIdx.x;
    for (int idx = t; idx < 1568; idx += 256) {            // 16 ch x 98 chunks of 8
        int ch = idx / 98, o = idx - ch * 98;
        *reinterpret_cast<uint4*>(sm + ch * 784 + o * 8) =
            *reinterpret_cast<const uint4*>(g_y1 + (size_t)(c0 + ch) * N1 + img * HW1 + o * 8);
    }
    __syncthreads();
    const __nv_bfloat16 bz = __float2bfloat16(0.f);
    for (int idx = t; idx < 7056; idx += 256) {            // 144 rows x 49 chunks of 4
        int row = idx / 49;
        int p4  = (idx - row * 49) * 4;
        int cl = row / 9, rs = row - cl * 9;
        int r = rs / 3, s = rs - r * 3;
        __nv_bfloat16 v[4];
        #pragma unroll
        for (int jj = 0; jj < 4; jj++) {
            int pix = p4 + jj;
            int oh = pix / 14, ow = pix - oh * 14;
            int ih = 2 * oh - 1 + r, iw = 2 * ow - 1 + s;
            v[jj] = ((unsigned)ih < 28u && (unsigned)iw < 28u) ? sm[cl * 784 + ih * 28 + iw] : bz;
        }
        *reinterpret_cast<uint2*>(g_im2 + (size_t)((c0 + cl) * 9 + rs) * N2 + img * HW2 + p4) =
            *reinterpret_cast<uint2*>(v);
    }
}

// ---------------- bf16 HMMA GEMM ---------------------------------------------
// BM=128 BN=128 BK=64, 4 warps @ 64x64, 3-stage cp.async, swizzle + ldmatrix.
#define STAGE 32768          // A 16KB + B 16KB
#define GSMEM (3 * STAGE)

template <int MODE>
__device__ __forceinline__ void chunk_params(int t, const __nv_bfloat16*& A,
                                             const __nv_bfloat16*& B, int& K, int& N,
                                             int& k0) {
    if (MODE == 0)      { A = g_w1q; B = g_xq;  K = CIN; N = N1; k0 = t * 64; }
    else if (MODE == 1) { A = g_w2q; B = g_im2; K = K2;  N = N2; k0 = t * 64; }
    else {
        if (t < 8) { A = g_wsq; B = g_xs; K = CIN; N = N2; k0 = t * 64; }
        else       { A = g_w3q; B = g_y2; K = PCH; N = N2; k0 = (t - 8) * 64; }
    }
}

template <int MODE>
__global__ __launch_bounds__(128, 2) void gemm_hmma(const float* __restrict__ bias,
                                                    const float* __restrict__ bias2,
                                                    float* __restrict__ out) {
    constexpr int TOT = (MODE == 0) ? 8 : (MODE == 1) ? 36 : 12;
    extern __shared__ __align__(128) unsigned char smem[];
    const uint32_t sb = smem_u32(smem);
    const int tid = threadIdx.x, warp = tid >> 5, lane = tid & 31;
    const int wr = warp & 1, wc = warp >> 1;      // warp tile: rows wr*64, cols wc*64
    const int qr = lane >> 2, qc = lane & 3;
    const int i8 = lane >> 3, rin = lane & 7;
    const int n0 = blockIdx.x * 128, m0 = blockIdx.y * 128;

    float acc[4][8][4];
    #pragma unroll
    for (int mi = 0; mi < 4; mi++)
        #pragma unroll
        for (int nj = 0; nj < 8; nj++)
            #pragma unroll
            for (int e = 0; e < 4; e++) acc[mi][nj][e] = 0.f;

    auto load_stage = [&](int t) {
        if (t >= TOT) return;
        const __nv_bfloat16 *A, *B; int K, N, k0;
        chunk_params<MODE>(t, A, B, K, N, k0);
        uint32_t st = sb + (t % 3) * STAGE;
        #pragma unroll
        for (int it = 0; it < 8; it++) {
            int idx = tid + it * 128;
            int row = idx >> 3, kk = idx & 7;
            uint32_t off = row * 128 + ((kk ^ (row & 7)) << 4);
            cp16s(st + off, A + (size_t)(m0 + row) * K + k0 + kk * 8);
        }
        #pragma unroll
        for (int it = 0; it < 8; it++) {
            int idx = tid + it * 128;
            int row = idx >> 4, nc = idx & 15;
            uint32_t off = row * 256 + ((nc ^ (row & 7)) << 4);
            cp16s(st + 16384 + off, B + (size_t)(k0 + row) * N + n0 + nc * 8);
        }
    };

    load_stage(0); CP_COMMIT;
    load_stage(1); CP_COMMIT;

    for (int i = 0; i < TOT; i++) {
        CP_WAIT1;                       // stage i arrived
        __syncthreads();                // all warps done with stage i-1
        load_stage(i + 2); CP_COMMIT;
        uint32_t abase = sb + (i % 3) * STAGE;
        uint32_t bbase = abase + 16384;
        #pragma unroll
        for (int ks = 0; ks < 4; ks++) {
            uint32_t a[4][4], b[8][2];
            #pragma unroll
            for (int mi = 0; mi < 4; mi++) {
                int row = wr * 64 + mi * 16 + (i8 & 1) * 8 + rin;
                int kk = ks * 2 + (i8 >> 1);
                ldsm_x4(a[mi], abase + row * 128 + ((kk ^ (row & 7)) << 4));
            }
            #pragma unroll
            for (int p = 0; p < 4; p++) {
                int krow = ks * 16 + ((i8 & 2) << 2) + rin;
                int nc = wc * 8 + p * 2 + (i8 & 1);
                uint32_t r[4];
                ldsm_x4t(r, bbase + krow * 256 + ((nc ^ (krow & 7)) << 4));
                b[2 * p][0] = r[0]; b[2 * p][1] = r[2];
                b[2 * p + 1][0] = r[1]; b[2 * p + 1][1] = r[3];
            }
            #pragma unroll
            for (int mi = 0; mi < 4; mi++)
                #pragma unroll
                for (int nj = 0; nj < 8; nj++)
                    hmma(acc[mi][nj], a[mi], b[nj][0], b[nj][1]);
        }
        if (MODE == 2 && i == 7) {
            // fold shortcut accumulator into conv3 units: acc *= css/c3s
            const float ratio = __uint_as_float(g_maxbits[3]) / __uint_as_float(g_maxbits[2]);
            #pragma unroll
            for (int mi = 0; mi < 4; mi++)
                #pragma unroll
                for (int nj = 0; nj < 8; nj++)
                    #pragma unroll
                    for (int e = 0; e < 4; e++) acc[mi][nj][e] *= ratio;
        }
    }
    __syncthreads();                    // tiles dead; reuse smem for staging

    // ---------------- epilogue ------------------------------------------------
    if (MODE == 0 || MODE == 1) {
        const float kmul = __uint_as_float(g_maxbits[MODE]) * (1.f / 16129.f);
        float qbv[4][2];
        #pragma unroll
        for (int mi = 0; mi < 4; mi++)
            #pragma unroll
            for (int h = 0; h < 2; h++) {
                int m = m0 + wr * 64 + mi * 16 + qr + h * 8;
                qbv[mi][h] = rintf(bias[m] * 127.f) * (2.f / 127.f);
            }
        uint16_t* stg = reinterpret_cast<uint16_t*>(smem);   // [128][136]
        #pragma unroll
        for (int mi = 0; mi < 4; mi++)
            #pragma unroll
            for (int nj = 0; nj < 8; nj++)
                #pragma unroll
                for (int e = 0; e < 4; e++) {
                    int ml = wr * 64 + mi * 16 + qr + (e >> 1) * 8;
                    int nl = wc * 64 + nj * 8 + qc * 2 + (e & 1);
                    float t = acc[mi][nj][e] * kmul + qbv[mi][e >> 1];
                    float y = rintf(fminf(fmaxf(t * 2.f, 0.f), 1.f) * 127.f);
                    __nv_bfloat16 bv = __float2bfloat16(y);
                    stg[ml * 136 + nl] = *reinterpret_cast<uint16_t*>(&bv);
                }
        __syncthreads();
        __nv_bfloat16* dst = (MODE == 0) ? g_y1 : g_y2;
        const size_t Nd = (MODE == 0) ? N1 : N2;
        for (int idx = tid; idx < 2048; idx += 128) {
            int row = idx >> 4, c = idx & 15;
            *reinterpret_cast<uint4*>(dst + (size_t)(m0 + row) * Nd + n0 + c * 8) =
                *reinterpret_cast<uint4*>(stg + row * 136 + c * 8);
        }
    } else {
        const float c2s = __uint_as_float(g_maxbits[1]);
        const float c3s = __uint_as_float(g_maxbits[2]);
        const float k3 = c3s * 0.5f * (1.f / 16129.f);
        const float bk3 = c3s / c2s;
        float bb[4][2];
        #pragma unroll
        for (int mi = 0; mi < 4; mi++)
            #pragma unroll
            for (int h = 0; h < 2; h++) {
                int m = m0 + wr * 64 + mi * 16 + qr + h * 8;
                bb[mi][h] = rintf(bias[m]  * 127.f) * (1.f / 127.f) * bk3
                          + rintf(bias2[m] * 127.f) * (1.f / 127.f);
            }
        float* stgf = reinterpret_cast<float*>(smem);   // [128][132]
        #pragma unroll
        for (int mi = 0; mi < 4; mi++)
            #pragma unroll
            for (int nj = 0; nj < 8; nj++)
                #pragma unroll
                for (int e = 0; e < 4; e++) {
                    int ml = wr * 64 + mi * 16 + qr + (e >> 1) * 8;
                    int nl = wc * 64 + nj * 8 + qc * 2 + (e & 1);
                    float v = acc[mi][nj][e] * k3 + bb[mi][e >> 1];
                    stgf[ml * 132 + nl] = fminf(fmaxf(v, 0.f), 6.f);
                }
        __syncthreads();
        for (int idx = tid; idx < 4096; idx += 128) {
            int row = idx >> 5, ch = idx & 31;
            int n = n0 + ch * 4;
            int img = n / HW2, pix = n - img * HW2;
            *reinterpret_cast<float4*>(out + ((size_t)img * COUT + m0 + row) * HW2 + pix) =
                *reinterpret_cast<float4*>(stgf + row * 132 + ch * 4);
        }
    }
}

// ---------------- launch ------------------------------------------------------
extern "C" void kernel_launch(void* const* d_in, const int* in_sizes, int n_in,
                              void* d_out, int out_size) {
    const float* x  = (const float*)d_in[0];
    const float* w1 = (const float*)d_in[1];
    const float* b1 = (const float*)d_in[2];
    const float* w2 = (const float*)d_in[3];
    const float* b2 = (const float*)d_in[4];
    const float* w3 = (const float*)d_in[5];
    const float* b3 = (const float*)d_in[6];
    const float* ws = (const float*)d_in[7];
    const float* bs = (const float*)d_in[8];
    float* out = (float*)d_out;

    static bool attr_set = false;
    if (!attr_set) {
        cudaFuncSetAttribute(gemm_hmma<0>, cudaFuncAttributeMaxDynamicSharedMemorySize, GSMEM);
        cudaFuncSetAttribute(gemm_hmma<1>, cudaFuncAttributeMaxDynamicSharedMemorySize, GSMEM);
        cudaFuncSetAttribute(gemm_hmma<2>, cudaFuncAttributeMaxDynamicSharedMemorySize, GSMEM);
        attr_set = true;
    }

    reset_kernel<<<1, 32>>>();
    maxabs_all<<<dim3(64, 4), 256>>>(w1, w2, w3, ws);
    quantw_all<<<dim3(160, 4), 256>>>(w1, w2, w3, ws);
    quantx<<<(BATCH * CIN * 196 + 255) / 256, 256>>>(x);

    gemm_hmma<0><<<dim3(N1 / 128, 2), 128, GSMEM>>>(b1, nullptr, nullptr);
    im2col_s<<<dim3(16, 64), 256>>>();
    gemm_hmma<1><<<dim3(N2 / 128, 2), 128, GSMEM>>>(b2, nullptr, nullptr);
    gemm_hmma<2><<<dim3(N2 / 128, 8), 128, GSMEM>>>(b3, bs, out);
}

// round 14
// speedup vs baseline: 1.0729x; 1.0729x over previous
#include <cuda_runtime.h>
#include <cuda_bf16.h>
#include <cstdint>

#define BATCH 64
#define CIN   512
#define PCH   256
#define COUT  1024
#define HW1   784
#define HW2   196
#define N1    (BATCH * HW1)   // 50176
#define N2    (BATCH * HW2)   // 12544
#define K2    (PCH * 9)       // 2304

// ---------------- scratch: ALL activations [K][N] row-major ------------------
__device__ __nv_bfloat16 g_xq [(size_t)CIN * N1];   // [c][n1]
__device__ __nv_bfloat16 g_xs [(size_t)CIN * N2];   // [c][n2]
__device__ __nv_bfloat16 g_y1 [(size_t)PCH * N1];   // [m][n1]
__device__ __nv_bfloat16 g_im2[(size_t)K2  * N2];   // [k][n2]
__device__ __nv_bfloat16 g_y2 [(size_t)PCH * N2];   // [m][n2]
__device__ __nv_bfloat16 g_w1q[PCH  * CIN];
__device__ __nv_bfloat16 g_w2q[PCH  * K2];
__device__ __nv_bfloat16 g_w3q[COUT * PCH];
__device__ __nv_bfloat16 g_wsq[COUT * CIN];
__device__ unsigned g_maxbits[4];

// ---------------- helpers -----------------------------------------------------
__device__ __forceinline__ uint32_t smem_u32(const void* p) {
    uint32_t a;
    asm("{ .reg .u64 t; cvta.to.shared.u64 t, %1; cvt.u32.u64 %0, t; }" : "=r"(a) : "l"(p));
    return a;
}
__device__ __forceinline__ void cp16s(uint32_t s, const void* g) {
    asm volatile("cp.async.cg.shared.global [%0],[%1],16;\n" :: "r"(s), "l"(g));
}
#define CP_COMMIT asm volatile("cp.async.commit_group;\n" ::: "memory")
#define CP_WAIT1  asm volatile("cp.async.wait_group 1;\n" ::: "memory")

__device__ __forceinline__ void ldsm_x4(uint32_t (&r)[4], uint32_t addr) {
    asm volatile("ldmatrix.sync.aligned.m8n8.x4.shared.b16 {%0,%1,%2,%3},[%4];\n"
                 : "=r"(r[0]), "=r"(r[1]), "=r"(r[2]), "=r"(r[3]) : "r"(addr));
}
__device__ __forceinline__ void ldsm_x4t(uint32_t (&r)[4], uint32_t addr) {
    asm volatile("ldmatrix.sync.aligned.m8n8.x4.trans.shared.b16 {%0,%1,%2,%3},[%4];\n"
                 : "=r"(r[0]), "=r"(r[1]), "=r"(r[2]), "=r"(r[3]) : "r"(addr));
}
__device__ __forceinline__ void hmma(float (&c)[4], const uint32_t (&a)[4],
                                     uint32_t b0, uint32_t b1) {
    asm volatile("mma.sync.aligned.m16n8k16.row.col.f32.bf16.bf16.f32 "
                 "{%0,%1,%2,%3},{%4,%5,%6,%7},{%8,%9},{%0,%1,%2,%3};\n"
                 : "+f"(c[0]), "+f"(c[1]), "+f"(c[2]), "+f"(c[3])
                 : "r"(a[0]), "r"(a[1]), "r"(a[2]), "r"(a[3]), "r"(b0), "r"(b1));
}

// ---------------- setup kernels ----------------------------------------------
__global__ void reset_kernel() {
    if (threadIdx.x < 4) g_maxbits[threadIdx.x] = 0u;
}

__global__ void maxabs_all(const float* __restrict__ w1, const float* __restrict__ w2,
                           const float* __restrict__ w3, const float* __restrict__ ws) {
    int slot = blockIdx.y;
    const float* src = slot == 0 ? w1 : slot == 1 ? w2 : slot == 2 ? w3 : ws;
    int n4 = (slot == 0 ? PCH * CIN : slot == 1 ? PCH * K2 : slot == 2 ? COUT * PCH : COUT * CIN) / 4;
    float m = 0.f;
    for (int i = blockIdx.x * blockDim.x + threadIdx.x; i < n4; i += gridDim.x * blockDim.x) {
        float4 v = reinterpret_cast<const float4*>(src)[i];
        m = fmaxf(m, fmaxf(fmaxf(fabsf(v.x), fabsf(v.y)), fmaxf(fabsf(v.z), fabsf(v.w))));
    }
    #pragma unroll
    for (int o = 16; o; o >>= 1) m = fmaxf(m, __shfl_xor_sync(0xffffffffu, m, o));
    __shared__ float sm[8];
    if ((threadIdx.x & 31) == 0) sm[threadIdx.x >> 5] = m;
    __syncthreads();
    if (threadIdx.x < 8) {
        m = sm[threadIdx.x];
        #pragma unroll
        for (int o = 4; o; o >>= 1) m = fmaxf(m, __shfl_xor_sync(0xffu, m, o));
        if (threadIdx.x == 0) atomicMax(&g_maxbits[slot], __float_as_uint(m));
    }
}

__global__ void quantw_all(const float* __restrict__ w1, const float* __restrict__ w2,
                           const float* __restrict__ w3, const float* __restrict__ ws) {
    int slot = blockIdx.y;
    const float* src = slot == 0 ? w1 : slot == 1 ? w2 : slot == 2 ? w3 : ws;
    __nv_bfloat16* dst = slot == 0 ? g_w1q : slot == 1 ? g_w2q : slot == 2 ? g_w3q : g_wsq;
    int n4 = (slot == 0 ? PCH * CIN : slot == 1 ? PCH * K2 : slot == 2 ? COUT * PCH : COUT * CIN) / 4;
    const float inv = 1.f / __uint_as_float(g_maxbits[slot]);
    for (int i = blockIdx.x * blockDim.x + threadIdx.x; i < n4; i += gridDim.x * blockDim.x) {
        float4 v = reinterpret_cast<const float4*>(src)[i];
        __nv_bfloat16 q[4];
        q[0] = __float2bfloat16(rintf(fminf(fmaxf(v.x * inv, -1.f), 1.f) * 127.f));
        q[1] = __float2bfloat16(rintf(fminf(fmaxf(v.y * inv, -1.f), 1.f) * 127.f));
        q[2] = __float2bfloat16(rintf(fminf(fmaxf(v.z * inv, -1.f), 1.f) * 127.f));
        q[3] = __float2bfloat16(rintf(fminf(fmaxf(v.w * inv, -1.f), 1.f) * 127.f));
        *reinterpret_cast<uint2*>(dst + (size_t)i * 4) = *reinterpret_cast<uint2*>(q);
    }
}

// streaming quantize: x[img][c][pix] -> g_xq[c][img*784+pix]; downsample -> g_xs
__global__ __launch_bounds__(256) void quantx(const float* __restrict__ x) {
    int idx = blockIdx.x * blockDim.x + threadIdx.x;   // (img, c, j) j = 4-pix chunk
    if (idx >= BATCH * CIN * 196) return;
    int j   = idx % 196;
    int c   = (idx / 196) % CIN;
    int img = idx / (196 * CIN);
    float4 v = *reinterpret_cast<const float4*>(x + ((size_t)img * CIN + c) * HW1 + j * 4);
    __nv_bfloat16 q[4];
    q[0] = __float2bfloat16(rintf(fminf(fmaxf(v.x * 2.f, -1.f), 1.f) * 127.f));
    q[1] = __float2bfloat16(rintf(fminf(fmaxf(v.y * 2.f, -1.f), 1.f) * 127.f));
    q[2] = __float2bfloat16(rintf(fminf(fmaxf(v.z * 2.f, -1.f), 1.f) * 127.f));
    q[3] = __float2bfloat16(rintf(fminf(fmaxf(v.w * 2.f, -1.f), 1.f) * 127.f));
    *reinterpret_cast<uint2*>(g_xq + (size_t)c * N1 + img * HW1 + j * 4) =
        *reinterpret_cast<uint2*>(q);
    int h = j / 7, w0 = (j % 7) * 4;     // 28 = 7 chunks * 4
    if (!(h & 1)) {
        __nv_bfloat16 d[2] = {q[0], q[2]};
        *reinterpret_cast<unsigned*>(g_xs + (size_t)c * N2 + img * HW2 +
                                     (h >> 1) * 14 + (w0 >> 1)) = *reinterpret_cast<unsigned*>(d);
    }
}

// smem-staged im2col: g_y1[c][n1] -> g_im2[c*9+rs][n2]
__global__ __launch_bounds__(256) void im2col_s() {
    __shared__ __nv_bfloat16 sm[16 * 784 + 8];
    int c0 = blockIdx.x * 16, img = blockIdx.y;
    int t = threadIdx.x;
    for (int idx = t; idx < 1568; idx += 256) {            // 16 ch x 98 chunks of 8
        int ch = idx / 98, o = idx - ch * 98;
        *reinterpret_cast<uint4*>(sm + ch * 784 + o * 8) =
            *reinterpret_cast<const uint4*>(g_y1 + (size_t)(c0 + ch) * N1 + img * HW1 + o * 8);
    }
    __syncthreads();
    const __nv_bfloat16 bz = __float2bfloat16(0.f);
    for (int idx = t; idx < 7056; idx += 256) {            // 144 rows x 49 chunks of 4
        int row = idx / 49;
        int p4  = (idx - row * 49) * 4;
        int cl = row / 9, rs = row - cl * 9;
        int r = rs / 3, s = rs - r * 3;
        __nv_bfloat16 v[4];
        #pragma unroll
        for (int jj = 0; jj < 4; jj++) {
            int pix = p4 + jj;
            int oh = pix / 14, ow = pix - oh * 14;
            int ih = 2 * oh - 1 + r, iw = 2 * ow - 1 + s;
            v[jj] = ((unsigned)ih < 28u && (unsigned)iw < 28u) ? sm[cl * 784 + ih * 28 + iw] : bz;
        }
        *reinterpret_cast<uint2*>(g_im2 + (size_t)((c0 + cl) * 9 + rs) * N2 + img * HW2 + p4) =
            *reinterpret_cast<uint2*>(v);
    }
}

// ---------------- bf16 HMMA GEMM ---------------------------------------------
// MODE 0/2: BM=128 BN=128, 256 thr (8 warps @ 32x64), 3-stage, 2 CTA/SM.
// MODE 1  : BM=128 BN=64,  128 thr (4 warps @ 32x64), 3-stage, 3 CTA/SM,
//           grid (196,2)=392 CTAs -> fixes conv2 wave quantization.
template <int MODE>
__device__ __forceinline__ void chunk_params(int t, const __nv_bfloat16*& A,
                                             const __nv_bfloat16*& B, int& K, int& N,
                                             int& k0) {
    if (MODE == 0)      { A = g_w1q; B = g_xq;  K = CIN; N = N1; k0 = t * 64; }
    else if (MODE == 1) { A = g_w2q; B = g_im2; K = K2;  N = N2; k0 = t * 64; }
    else {
        if (t < 8) { A = g_wsq; B = g_xs; K = CIN; N = N2; k0 = t * 64; }
        else       { A = g_w3q; B = g_y2; K = PCH; N = N2; k0 = (t - 8) * 64; }
    }
}

template <int MODE>
__global__ __launch_bounds__(MODE == 1 ? 128 : 256, MODE == 1 ? 3 : 2)
void gemm_hmma(const float* __restrict__ bias, const float* __restrict__ bias2,
               float* __restrict__ out) {
    constexpr int TOT     = (MODE == 0) ? 8 : (MODE == 1) ? 36 : 12;
    constexpr int THREADS = (MODE == 1) ? 128 : 256;
    constexpr int BNT     = (MODE == 1) ? 64 : 128;
    constexpr int BROW    = BNT * 2;            // B smem row bytes
    constexpr int BCH     = BNT / 8;            // 16B chunks per B row
    constexpr int STAGE   = 16384 + 64 * BROW;  // A 16KB + B
    extern __shared__ __align__(128) unsigned char smem[];
    const uint32_t sb = smem_u32(smem);
    const int tid = threadIdx.x, warp = tid >> 5, lane = tid & 31;
    const int wr = (MODE == 1) ? warp : (warp >> 1);
    const int wc = (MODE == 1) ? 0 : (warp & 1);
    const int qr = lane >> 2, qc = lane & 3;
    const int i8 = lane >> 3, rin = lane & 7;
    const int n0 = blockIdx.x * BNT, m0 = blockIdx.y * 128;

    float acc[2][8][4];
    #pragma unroll
    for (int mi = 0; mi < 2; mi++)
        #pragma unroll
        for (int nj = 0; nj < 8; nj++)
            #pragma unroll
            for (int e = 0; e < 4; e++) acc[mi][nj][e] = 0.f;

    auto load_stage = [&](int t) {
        if (t >= TOT) return;
        const __nv_bfloat16 *A, *B; int K, N, k0;
        chunk_params<MODE>(t, A, B, K, N, k0);
        uint32_t st = sb + (t % 3) * STAGE;
        #pragma unroll
        for (int it = 0; it < 1024 / THREADS; it++) {      // A: 128 rows x 8 chunks
            int idx = tid + it * THREADS;
            int row = idx >> 3, kk = idx & 7;
            uint32_t off = row * 128 + ((kk ^ (row & 7)) << 4);
            cp16s(st + off, A + (size_t)(m0 + row) * K + k0 + kk * 8);
        }
        #pragma unroll
        for (int it = 0; it < 64 * BCH / THREADS; it++) {  // B: 64 rows x BCH chunks
            int idx = tid + it * THREADS;
            int row = idx / BCH, nc = idx % BCH;
            uint32_t off = row * BROW + ((nc ^ (row & 7)) << 4);
            cp16s(st + 16384 + off, B + (size_t)(k0 + row) * N + n0 + nc * 8);
        }
    };

    load_stage(0); CP_COMMIT;
    load_stage(1); CP_COMMIT;

    for (int i = 0; i < TOT; i++) {
        CP_WAIT1;                       // stage i arrived
        __syncthreads();                // all warps done with stage i-1
        load_stage(i + 2); CP_COMMIT;
        uint32_t abase = sb + (i % 3) * STAGE;
        uint32_t bbase = abase + 16384;
        #pragma unroll
        for (int ks = 0; ks < 4; ks++) {
            uint32_t a[2][4], b[8][2];
            #pragma unroll
            for (int mi = 0; mi < 2; mi++) {
                int row = wr * 32 + mi * 16 + (i8 & 1) * 8 + rin;
                int kk = ks * 2 + (i8 >> 1);
                ldsm_x4(a[mi], abase + row * 128 + ((kk ^ (row & 7)) << 4));
            }
            #pragma unroll
            for (int p = 0; p < 4; p++) {
                int krow = ks * 16 + ((i8 & 2) << 2) + rin;
                int nc = wc * 8 + p * 2 + (i8 & 1);
                uint32_t r[4];
                ldsm_x4t(r, bbase + krow * BROW + ((nc ^ (krow & 7)) << 4));
                b[2 * p][0] = r[0]; b[2 * p][1] = r[2];
                b[2 * p + 1][0] = r[1]; b[2 * p + 1][1] = r[3];
            }
            #pragma unroll
            for (int mi = 0; mi < 2; mi++)
                #pragma unroll
                for (int nj = 0; nj < 8; nj++)
                    hmma(acc[mi][nj], a[mi], b[nj][0], b[nj][1]);
        }
        if (MODE == 2 && i == 7) {
            // fold shortcut accumulator into conv3 units: acc *= css/c3s
            const float ratio = __uint_as_float(g_maxbits[3]) / __uint_as_float(g_maxbits[2]);
            #pragma unroll
            for (int mi = 0; mi < 2; mi++)
                #pragma unroll
                for (int nj = 0; nj < 8; nj++)
                    #pragma unroll
                    for (int e = 0; e < 4; e++) acc[mi][nj][e] *= ratio;
        }
    }
    __syncthreads();                    // tiles dead; reuse smem for staging

    // ---------------- epilogue ------------------------------------------------
    if (MODE == 0 || MODE == 1) {
        constexpr int BSTG = BNT + 8;
        const float kmul = __uint_as_float(g_maxbits[MODE]) * (1.f / 16129.f);
        float qbv[2][2];
        #pragma unroll
        for (int mi = 0; mi < 2; mi++)
            #pragma unroll
            for (int h = 0; h < 2; h++) {
                int m = m0 + wr * 32 + mi * 16 + qr + h * 8;
                qbv[mi][h] = rintf(bias[m] * 127.f) * (2.f / 127.f);
            }
        uint16_t* stg = reinterpret_cast<uint16_t*>(smem);   // [128][BSTG]
        #pragma unroll
        for (int mi = 0; mi < 2; mi++)
            #pragma unroll
            for (int nj = 0; nj < 8; nj++)
                #pragma unroll
                for (int e = 0; e < 4; e++) {
                    int ml = wr * 32 + mi * 16 + qr + (e >> 1) * 8;
                    int nl = wc * 64 + nj * 8 + qc * 2 + (e & 1);
                    float t = acc[mi][nj][e] * kmul + qbv[mi][e >> 1];
                    float y = rintf(fminf(fmaxf(t * 2.f, 0.f), 1.f) * 127.f);
                    __nv_bfloat16 bv = __float2bfloat16(y);
                    stg[ml * BSTG + nl] = *reinterpret_cast<uint16_t*>(&bv);
                }
        __syncthreads();
        __nv_bfloat16* dst = (MODE == 0) ? g_y1 : g_y2;
        const size_t Nd = (MODE == 0) ? N1 : N2;
        #pragma unroll
        for (int it = 0; it < 128 * BCH / THREADS; it++) {
            int idx = tid + it * THREADS;
            int row = idx / BCH, c = idx % BCH;
            *reinterpret_cast<uint4*>(dst + (size_t)(m0 + row) * Nd + n0 + c * 8) =
                *reinterpret_cast<uint4*>(stg + row * BSTG + c * 8);
        }
    } else {
        const float c2s = __uint_as_float(g_maxbits[1]);
        const float c3s = __uint_as_float(g_maxbits[2]);
        const float k3 = c3s * 0.5f * (1.f / 16129.f);
        const float bk3 = c3s / c2s;
        float bb[2][2];
        #pragma unroll
        for (int mi = 0; mi < 2; mi++)
            #pragma unroll
            for (int h = 0; h < 2; h++) {
                int m = m0 + wr * 32 + mi * 16 + qr + h * 8;
                bb[mi][h] = rintf(bias[m]  * 127.f) * (1.f / 127.f) * bk3
                          + rintf(bias2[m] * 127.f) * (1.f / 127.f);
            }
        float* stgf = reinterpret_cast<float*>(smem);   // [128][132]
        #pragma unroll
        for (int mi = 0; mi < 2; mi++)
            #pragma unroll
            for (int nj = 0; nj < 8; nj++)
                #pragma unroll
                for (int e = 0; e < 4; e++) {
                    int ml = wr * 32 + mi * 16 + qr + (e >> 1) * 8;
                    int nl = wc * 64 + nj * 8 + qc * 2 + (e & 1);
                    float v = acc[mi][nj][e] * k3 + bb[mi][e >> 1];
                    stgf[ml * 132 + nl] = fminf(fmaxf(v, 0.f), 6.f);
                }
        __syncthreads();
        for (int idx = tid; idx < 4096; idx += 256) {
            int row = idx >> 5, ch = idx & 31;
            int n = n0 + ch * 4;
            int img = n / HW2, pix = n - img * HW2;
            *reinterpret_cast<float4*>(out + ((size_t)img * COUT + m0 + row) * HW2 + pix) =
                *reinterpret_cast<float4*>(stgf + row * 132 + ch * 4);
        }
    }
}

// ---------------- launch ------------------------------------------------------
extern "C" void kernel_launch(void* const* d_in, const int* in_sizes, int n_in,
                              void* d_out, int out_size) {
    const float* x  = (const float*)d_in[0];
    const float* w1 = (const float*)d_in[1];
    const float* b1 = (const float*)d_in[2];
    const float* w2 = (const float*)d_in[3];
    const float* b2 = (const float*)d_in[4];
    const float* w3 = (const float*)d_in[5];
    const float* b3 = (const float*)d_in[6];
    const float* ws = (const float*)d_in[7];
    const float* bs = (const float*)d_in[8];
    float* out = (float*)d_out;

    constexpr int GS_BIG = 3 * (16384 + 16384);   // 96 KB (MODE 0/2)
    constexpr int GS_C2  = 3 * (16384 + 8192);    // 72 KB (MODE 1)

    static bool attr_set = false;
    if (!attr_set) {
        cudaFuncSetAttribute(gemm_hmma<0>, cudaFuncAttributeMaxDynamicSharedMemorySize, GS_BIG);
        cudaFuncSetAttribute(gemm_hmma<1>, cudaFuncAttributeMaxDynamicSharedMemorySize, GS_C2);
        cudaFuncSetAttribute(gemm_hmma<2>, cudaFuncAttributeMaxDynamicSharedMemorySize, GS_BIG);
        attr_set = true;
    }

    reset_kernel<<<1, 32>>>();
    maxabs_all<<<dim3(64, 4), 256>>>(w1, w2, w3, ws);
    quantw_all<<<dim3(160, 4), 256>>>(w1, w2, w3, ws);
    quantx<<<(BATCH * CIN * 196 + 255) / 256, 256>>>(x);

    gemm_hmma<0><<<dim3(N1 / 128, 2), 256, GS_BIG>>>(b1, nullptr, nullptr);
    im2col_s<<<dim3(16, 64), 256>>>();
    gemm_hmma<1><<<dim3(N2 / 64, 2), 128, GS_C2>>>(b2, nullptr, nullptr);
    gemm_hmma<2><<<dim3(N2 / 128, 8), 256, GS_BIG>>>(b3, bs, out);
}